// round 1
// baseline (speedup 1.0000x reference)
#include <cuda_runtime.h>
#include <math.h>

#define DIM 128
#define HEADS 4
#define CH 32
#define NEG_SLOPE 0.2f
#define MAX_N 50000
#define MAX_E 600000

// ------------------- scratch (static device globals; no allocs) -------------------
__device__ float g_h[MAX_N * DIM];      // transformed features (per layer, reused)
__device__ float g_skip[MAX_N * DIM];   // x @ Wskip (per layer, reused)
__device__ float g_buf1[MAX_N * DIM];   // layer-1 output
__device__ float g_asrc[MAX_N * HEADS];
__device__ float g_adst[MAX_N * HEADS];
__device__ int   g_deg[MAX_N];
__device__ int   g_off[MAX_N + 1];
__device__ int   g_cursor[MAX_N];
__device__ int   g_csr[MAX_E + MAX_N];  // src node id per incoming edge (incl self-loop)

// ------------------- CSR build -------------------
__global__ void init_deg_kernel(int N) {
    int i = blockIdx.x * blockDim.x + threadIdx.x;
    if (i < N) g_deg[i] = 1;  // self-loop
}

__global__ void hist_kernel(const int* __restrict__ dst, int E) {
    int i = blockIdx.x * blockDim.x + threadIdx.x;
    if (i < E) atomicAdd(&g_deg[dst[i]], 1);
}

// single-block scan (N ~ 50k, 49 chunks of 1024)
__global__ void scan_kernel(int N) {
    __shared__ int sh[1024];
    __shared__ int carry;
    int tid = threadIdx.x;
    if (tid == 0) { carry = 0; g_off[0] = 0; }
    __syncthreads();
    for (int base = 0; base < N; base += 1024) {
        int i = base + tid;
        int v = (i < N) ? g_deg[i] : 0;
        sh[tid] = v;
        __syncthreads();
        #pragma unroll
        for (int o = 1; o < 1024; o <<= 1) {
            int t = (tid >= o) ? sh[tid - o] : 0;
            __syncthreads();
            sh[tid] += t;
            __syncthreads();
        }
        int incl = sh[tid];
        int c = carry;
        if (i < N) {
            g_off[i + 1]  = c + incl;
            g_cursor[i]   = c + incl - v;  // exclusive prefix = segment start
        }
        __syncthreads();
        if (tid == 0) carry = c + sh[1023];
        __syncthreads();
    }
}

__global__ void scatter_kernel(const int* __restrict__ src, const int* __restrict__ dst,
                               int E, int N) {
    int i = blockIdx.x * blockDim.x + threadIdx.x;
    if (i < E) {
        int d = dst[i];
        int p = atomicAdd(&g_cursor[d], 1);
        g_csr[p] = src[i];
    } else if (i < E + N) {
        int n = i - E;
        int p = atomicAdd(&g_cursor[n], 1);
        g_csr[p] = n;  // self loop
    }
}

// ------------------- GEMM: Y[nrows,128] = X[nrows,128] @ W[128,128] -------------------
// 256 threads, 64 rows/block, 8x4 per-thread tile, K chunked by 32 through smem.
__global__ void __launch_bounds__(256, 4)
gemm_kernel(const float* __restrict__ X, const float* __restrict__ W,
            float* __restrict__ Y, int nrows) {
    __shared__ float xs[64 * 32];
    __shared__ float ws[32 * 128];
    int tid = threadIdx.x;
    int row0 = blockIdx.x * 64;
    int ty = tid >> 5;    // 0..7
    int tx = tid & 31;    // 0..31

    float acc[8][4];
    #pragma unroll
    for (int i = 0; i < 8; i++)
        #pragma unroll
        for (int j = 0; j < 4; j++) acc[i][j] = 0.0f;

    for (int kc = 0; kc < 4; kc++) {
        // load x tile: 64 rows x 32 k = 512 float4
        #pragma unroll
        for (int t = 0; t < 2; t++) {
            int idx = tid + t * 256;          // float4 index 0..511
            int r = idx >> 3;                 // 0..63
            int kk = idx & 7;                 // 0..7
            float4 v = make_float4(0.f, 0.f, 0.f, 0.f);
            if (row0 + r < nrows)
                v = ((const float4*)X)[(size_t)(row0 + r) * 32 + kc * 8 + kk];
            ((float4*)xs)[r * 8 + kk] = v;
        }
        // load W chunk: 32 k-rows x 128 = 1024 float4
        #pragma unroll
        for (int t = 0; t < 4; t++) {
            int idx = tid + t * 256;          // 0..1023
            int k = idx >> 5;                 // 0..31
            int c4 = idx & 31;                // 0..31
            ((float4*)ws)[idx] = ((const float4*)W)[(size_t)(kc * 32 + k) * 32 + c4];
        }
        __syncthreads();
        #pragma unroll
        for (int k = 0; k < 32; k++) {
            float4 b = ((float4*)ws)[k * 32 + tx];
            float a[8];
            #pragma unroll
            for (int i = 0; i < 8; i++) a[i] = xs[(ty * 8 + i) * 32 + k];
            #pragma unroll
            for (int i = 0; i < 8; i++) {
                acc[i][0] += a[i] * b.x;
                acc[i][1] += a[i] * b.y;
                acc[i][2] += a[i] * b.z;
                acc[i][3] += a[i] * b.w;
            }
        }
        __syncthreads();
    }
    #pragma unroll
    for (int i = 0; i < 8; i++) {
        int r = row0 + ty * 8 + i;
        if (r < nrows) {
            float4 o = make_float4(acc[i][0], acc[i][1], acc[i][2], acc[i][3]);
            ((float4*)Y)[(size_t)r * 32 + tx] = o;
        }
    }
}

// ------------------- per-node attention logits: asrc/adst [N,H] -------------------
// warp per node; lane owns 4 consecutive channels (flat index lane*4..lane*4+3),
// which sit entirely inside head = lane>>3.
__global__ void att_kernel(const float* __restrict__ a_src, const float* __restrict__ a_dst,
                           int N) {
    int gw = (blockIdx.x * blockDim.x + threadIdx.x) >> 5;
    int lane = threadIdx.x & 31;
    if (gw >= N) return;
    int n = gw;
    float4 hv = ((const float4*)g_h)[(size_t)n * 32 + lane];
    float4 s4 = ((const float4*)a_src)[lane];
    float4 d4 = ((const float4*)a_dst)[lane];
    float ps = hv.x * s4.x + hv.y * s4.y + hv.z * s4.z + hv.w * s4.w;
    float pd = hv.x * d4.x + hv.y * d4.y + hv.z * d4.z + hv.w * d4.w;
    #pragma unroll
    for (int o = 4; o > 0; o >>= 1) {
        ps += __shfl_down_sync(0xffffffffu, ps, o, 8);
        pd += __shfl_down_sync(0xffffffffu, pd, o, 8);
    }
    if ((lane & 7) == 0) {
        int head = lane >> 3;
        g_asrc[n * 4 + head] = ps;
        g_adst[n * 4 + head] = pd;
    }
}

// ------------------- softmax-aggregate + skip + bias + elu -------------------
// warp per node. Pass A: segment max per head. Pass B: exp-weighted sum of h[src].
__global__ void __launch_bounds__(256)
agg_kernel(const float* __restrict__ bias, float* __restrict__ out, int N) {
    int gw = (blockIdx.x * blockDim.x + threadIdx.x) >> 5;
    int lane = threadIdx.x & 31;
    if (gw >= N) return;
    int n = gw;
    int beg = g_off[n];
    int end = g_off[n + 1];
    int head = lane >> 3;

    float ad0 = g_adst[n * 4 + 0];
    float ad1 = g_adst[n * 4 + 1];
    float ad2 = g_adst[n * 4 + 2];
    float ad3 = g_adst[n * 4 + 3];

    // Pass A: per-head max over incoming edges
    float m0 = -INFINITY, m1 = -INFINITY, m2 = -INFINITY, m3 = -INFINITY;
    for (int i = beg + lane; i < end; i += 32) {
        int s = g_csr[i];
        float4 as = ((const float4*)g_asrc)[s];
        float e0 = as.x + ad0; e0 = (e0 > 0.f) ? e0 : NEG_SLOPE * e0;
        float e1 = as.y + ad1; e1 = (e1 > 0.f) ? e1 : NEG_SLOPE * e1;
        float e2 = as.z + ad2; e2 = (e2 > 0.f) ? e2 : NEG_SLOPE * e2;
        float e3 = as.w + ad3; e3 = (e3 > 0.f) ? e3 : NEG_SLOPE * e3;
        m0 = fmaxf(m0, e0); m1 = fmaxf(m1, e1); m2 = fmaxf(m2, e2); m3 = fmaxf(m3, e3);
    }
    #pragma unroll
    for (int o = 16; o > 0; o >>= 1) {
        m0 = fmaxf(m0, __shfl_xor_sync(0xffffffffu, m0, o));
        m1 = fmaxf(m1, __shfl_xor_sync(0xffffffffu, m1, o));
        m2 = fmaxf(m2, __shfl_xor_sync(0xffffffffu, m2, o));
        m3 = fmaxf(m3, __shfl_xor_sync(0xffffffffu, m3, o));
    }
    float mh  = (head == 0) ? m0 : (head == 1) ? m1 : (head == 2) ? m2 : m3;
    float adh = (head == 0) ? ad0 : (head == 1) ? ad1 : (head == 2) ? ad2 : ad3;

    // Pass B: exp-weighted aggregation (edge-serial, channel-parallel)
    float denom = 0.0f;
    float4 acc = make_float4(0.f, 0.f, 0.f, 0.f);
    const float4* h4 = (const float4*)g_h;
    for (int j = beg; j < end; j++) {
        int s = g_csr[j];                              // broadcast
        float a = g_asrc[s * 4 + head];                // 4 distinct addrs / warp
        float e = a + adh; e = (e > 0.f) ? e : NEG_SLOPE * e;
        float w = __expf(e - mh);
        denom += w;
        float4 v = h4[(size_t)s * 32 + lane];          // coalesced 512B/warp
        acc.x += w * v.x; acc.y += w * v.y; acc.z += w * v.z; acc.w += w * v.w;
    }
    float inv = 1.0f / (denom + 1e-16f);
    float4 b  = ((const float4*)bias)[lane];
    float4 sk = ((const float4*)g_skip)[(size_t)n * 32 + lane];
    float4 o;
    o.x = acc.x * inv + b.x + sk.x;
    o.y = acc.y * inv + b.y + sk.y;
    o.z = acc.z * inv + b.z + sk.z;
    o.w = acc.w * inv + b.w + sk.w;
    // elu (alpha=1)
    o.x = (o.x > 0.f) ? o.x : expm1f(o.x);
    o.y = (o.y > 0.f) ? o.y : expm1f(o.y);
    o.z = (o.z > 0.f) ? o.z : expm1f(o.z);
    o.w = (o.w > 0.f) ? o.w : expm1f(o.w);
    ((float4*)out)[(size_t)n * 32 + lane] = o;
}

// ------------------- launch -------------------
extern "C" void kernel_launch(void* const* d_in, const int* in_sizes, int n_in,
                              void* d_out, int out_size) {
    const float* x    = (const float*)d_in[0];
    const int*   ei   = (const int*)  d_in[1];
    const float* W1   = (const float*)d_in[2];
    const float* as1  = (const float*)d_in[3];
    const float* ad1  = (const float*)d_in[4];
    const float* b1   = (const float*)d_in[5];
    const float* Ws1  = (const float*)d_in[6];
    const float* W2   = (const float*)d_in[7];
    const float* as2  = (const float*)d_in[8];
    const float* ad2  = (const float*)d_in[9];
    const float* b2   = (const float*)d_in[10];
    const float* Ws2  = (const float*)d_in[11];

    int N = in_sizes[0] / DIM;
    int E = in_sizes[1] / 2;
    const int* src = ei;
    const int* dst = ei + E;

    // --- CSR build (shared by both layers) ---
    init_deg_kernel<<<(N + 255) / 256, 256>>>(N);
    hist_kernel<<<(E + 255) / 256, 256>>>(dst, E);
    scan_kernel<<<1, 1024>>>(N);
    scatter_kernel<<<(E + N + 255) / 256, 256>>>(src, dst, E, N);

    int gemm_blocks = (N + 63) / 64;
    int warp_blocks = (N * 32 + 255) / 256;

    float* buf1 = nullptr;
    cudaGetSymbolAddress((void**)&buf1, g_buf1);
    float* hbuf = nullptr;
    cudaGetSymbolAddress((void**)&hbuf, g_h);
    float* sbuf = nullptr;
    cudaGetSymbolAddress((void**)&sbuf, g_skip);

    // --- layer 1 ---
    gemm_kernel<<<gemm_blocks, 256>>>(x, W1, hbuf, N);
    gemm_kernel<<<gemm_blocks, 256>>>(x, Ws1, sbuf, N);
    att_kernel<<<warp_blocks, 256>>>(as1, ad1, N);
    agg_kernel<<<warp_blocks, 256>>>(b1, buf1, N);

    // --- layer 2 ---
    gemm_kernel<<<gemm_blocks, 256>>>(buf1, W2, hbuf, N);
    gemm_kernel<<<gemm_blocks, 256>>>(buf1, Ws2, sbuf, N);
    att_kernel<<<warp_blocks, 256>>>(as2, ad2, N);
    agg_kernel<<<warp_blocks, 256>>>(b2, (float*)d_out, N);
}

// round 3
// speedup vs baseline: 1.4243x; 1.4243x over previous
#include <cuda_runtime.h>
#include <cuda_bf16.h>
#include <stdint.h>
#include <math.h>

#define DIM 128
#define HEADS 4
#define NEG_SLOPE 0.2f
#define MAX_N 50000
#define MAX_E 600000

// ------------------- scratch (static device globals; no allocs) -------------------
__device__ float g_h[MAX_N * DIM];
__device__ float g_skip[MAX_N * DIM];
__device__ float g_buf1[MAX_N * DIM];
__device__ float g_asrc[MAX_N * HEADS];
__device__ float g_adst[MAX_N * HEADS];
__device__ int   g_deg[MAX_N];
__device__ int   g_off[MAX_N + 1];
__device__ int   g_cursor[MAX_N];
__device__ int   g_csr[MAX_E + MAX_N];
// combined transposed weights per layer: Bt[n][k]: n<128 -> W[k][n], else Wskip[k][n-128]
__device__ __nv_bfloat16 g_bhi[2 * 256 * 128];
__device__ __nv_bfloat16 g_blo[2 * 256 * 128];

// ------------------- weight prep -------------------
__global__ void prep_weights(const float* __restrict__ W1, const float* __restrict__ Ws1,
                             const float* __restrict__ W2, const float* __restrict__ Ws2) {
    int idx = blockIdx.x * blockDim.x + threadIdx.x;
    if (idx >= 2 * 256 * 128) return;
    int layer = idx >> 15;
    int rem   = idx & 32767;
    int n     = rem >> 7;
    int k     = rem & 127;
    const float* W = layer ? (n < 128 ? W2 : Ws2) : (n < 128 ? W1 : Ws1);
    float v = W[k * 128 + (n & 127)];
    __nv_bfloat16 hi = __float2bfloat16(v);
    float lo = v - __bfloat162float(hi);
    g_bhi[idx] = hi;
    g_blo[idx] = __float2bfloat16(lo);
}

// ------------------- CSR build -------------------
__global__ void init_deg_kernel(int N) {
    int i = blockIdx.x * blockDim.x + threadIdx.x;
    if (i < N) g_deg[i] = 1;
}

__global__ void hist_kernel(const int* __restrict__ dst, int E) {
    int i = blockIdx.x * blockDim.x + threadIdx.x;
    if (i < E) atomicAdd(&g_deg[dst[i]], 1);
}

__global__ void scan_kernel(int N) {
    __shared__ int sh[1024];
    __shared__ int carry;
    int tid = threadIdx.x;
    if (tid == 0) { carry = 0; g_off[0] = 0; }
    __syncthreads();
    for (int base = 0; base < N; base += 1024) {
        int i = base + tid;
        int v = (i < N) ? g_deg[i] : 0;
        sh[tid] = v;
        __syncthreads();
        #pragma unroll
        for (int o = 1; o < 1024; o <<= 1) {
            int t = (tid >= o) ? sh[tid - o] : 0;
            __syncthreads();
            sh[tid] += t;
            __syncthreads();
        }
        int incl = sh[tid];
        int c = carry;
        if (i < N) {
            g_off[i + 1] = c + incl;
            g_cursor[i]  = c + incl - v;
        }
        __syncthreads();
        if (tid == 0) carry = c + sh[1023];
        __syncthreads();
    }
}

__global__ void scatter_kernel(const int* __restrict__ src, const int* __restrict__ dst,
                               int E, int N) {
    int i = blockIdx.x * blockDim.x + threadIdx.x;
    if (i < E) {
        int d = dst[i];
        int p = atomicAdd(&g_cursor[d], 1);
        g_csr[p] = src[i];
    } else if (i < E + N) {
        int n = i - E;
        int p = atomicAdd(&g_cursor[n], 1);
        g_csr[p] = n;
    }
}

// ------------------- HMMA helper -------------------
__device__ __forceinline__ void mma_bf16(float c[4], const uint32_t a[4], const uint32_t b[2]) {
    asm volatile(
        "mma.sync.aligned.m16n8k16.row.col.f32.bf16.bf16.f32 "
        "{%0,%1,%2,%3}, {%4,%5,%6,%7}, {%8,%9}, {%0,%1,%2,%3};"
        : "+f"(c[0]), "+f"(c[1]), "+f"(c[2]), "+f"(c[3])
        : "r"(a[0]), "r"(a[1]), "r"(a[2]), "r"(a[3]), "r"(b[0]), "r"(b[1]));
}

// ------------------- fused HMMA GEMM (h + skip) + attention logits -------------------
// CTA: 256 threads, tile M=64 x N=256. D = Xtile @ Bt^T via bf16 hi/lo 3-product split.
// Warp w: mi = w&1 (32 rows), ni = w>>1 (64 cols). ni<2 -> g_h + att dots; ni>=2 -> g_skip.
// smem (u32 words): A_hi[64*68], A_lo[64*68], B_hi[256*36], B_lo[256*36] (K chunked by 64).
__global__ void __launch_bounds__(256, 2)
gat_mma_fused(const float* __restrict__ X,
              const uint32_t* __restrict__ Bhi, const uint32_t* __restrict__ Blo,
              const float* __restrict__ a_src, const float* __restrict__ a_dst,
              int nrows) {
    extern __shared__ uint32_t dsm[];
    __shared__ float s_att[256];
    uint32_t* Ah = dsm;            // 64*68 = 4352
    uint32_t* Al = dsm + 4352;
    uint32_t* Bh = dsm + 8704;     // 256*36 = 9216
    uint32_t* Bl = dsm + 17920;

    int tid  = threadIdx.x;
    int row0 = blockIdx.x * 64;
    if (tid < 128) { s_att[tid] = a_src[tid]; s_att[128 + tid] = a_dst[tid]; }

    // ---- stage A (full K=128), fp32 -> bf16 hi/lo ----
    #pragma unroll
    for (int it = 0; it < 16; it++) {
        int idx = tid + it * 256;          // 0..4095
        int r = idx >> 6;
        int w = idx & 63;
        float x0 = 0.f, x1 = 0.f;
        int gr = row0 + r;
        if (gr < nrows) {
            float2 v = *(const float2*)(X + (size_t)gr * 128 + w * 2);
            x0 = v.x; x1 = v.y;
        }
        __nv_bfloat16 h0 = __float2bfloat16(x0);
        __nv_bfloat16 h1 = __float2bfloat16(x1);
        __nv_bfloat16 l0 = __float2bfloat16(x0 - __bfloat162float(h0));
        __nv_bfloat16 l1 = __float2bfloat16(x1 - __bfloat162float(h1));
        Ah[r * 68 + w] = ((uint32_t)__bfloat16_as_ushort(h1) << 16) | __bfloat16_as_ushort(h0);
        Al[r * 68 + w] = ((uint32_t)__bfloat16_as_ushort(l1) << 16) | __bfloat16_as_ushort(l0);
    }

    int lane = tid & 31, warp = tid >> 5;
    int mi = warp & 1, ni = warp >> 1;
    int g = lane >> 2, t = lane & 3;
    int mloc  = mi * 32;
    int nbase = ni * 64;

    float acc[2][8][4];
    #pragma unroll
    for (int a = 0; a < 2; a++)
        #pragma unroll
        for (int b = 0; b < 8; b++)
            #pragma unroll
            for (int c = 0; c < 4; c++) acc[a][b][c] = 0.f;

    for (int kc = 0; kc < 2; kc++) {
        if (kc) __syncthreads();
        // stage B chunk (256 rows x 32 words), hi+lo
        #pragma unroll
        for (int it = 0; it < 32; it++) {
            int idx = tid + it * 256;      // 0..8191
            int r = idx >> 5;
            int w = idx & 31;
            Bh[r * 36 + w] = Bhi[r * 64 + kc * 32 + w];
            Bl[r * 36 + w] = Blo[r * 64 + kc * 32 + w];
        }
        __syncthreads();

        #pragma unroll
        for (int p = 0; p < 3; p++) {
            const uint32_t* As = (p == 2) ? Al : Ah;
            const uint32_t* Bs = (p == 1) ? Bl : Bh;
            #pragma unroll
            for (int ksl = 0; ksl < 4; ksl++) {
                int aw = kc * 32 + ksl * 8 + t;
                uint32_t af[2][4];
                #pragma unroll
                for (int mt = 0; mt < 2; mt++) {
                    int rb = (mloc + mt * 16 + g) * 68;
                    af[mt][0] = As[rb + aw];
                    af[mt][1] = As[rb + 8 * 68 + aw];
                    af[mt][2] = As[rb + aw + 4];
                    af[mt][3] = As[rb + 8 * 68 + aw + 4];
                }
                int bw = ksl * 8 + t;
                #pragma unroll
                for (int nt = 0; nt < 8; nt++) {
                    uint32_t bf[2];
                    int rb = (nbase + nt * 8 + g) * 36;
                    bf[0] = Bs[rb + bw];
                    bf[1] = Bs[rb + bw + 4];
                    mma_bf16(acc[0][nt], af[0], bf);
                    mma_bf16(acc[1][nt], af[1], bf);
                }
            }
        }
    }

    // ---- epilogue ----
    int gr0 = row0 + mloc;
    if (ni < 2) {
        float ps[2][2][2], pd[2][2][2];
        #pragma unroll
        for (int a = 0; a < 2; a++)
            #pragma unroll
            for (int b = 0; b < 2; b++) {
                ps[a][b][0] = ps[a][b][1] = 0.f;
                pd[a][b][0] = pd[a][b][1] = 0.f;
            }
        #pragma unroll
        for (int mt = 0; mt < 2; mt++) {
            int r0 = gr0 + mt * 16 + g;
            int r1 = r0 + 8;
            #pragma unroll
            for (int nt = 0; nt < 8; nt++) {
                int col = nbase + nt * 8 + t * 2;
                int hh = nt >> 2;
                float s0 = s_att[col],     s1 = s_att[col + 1];
                float d0 = s_att[128 + col], d1 = s_att[128 + col + 1];
                ps[mt][0][hh] += acc[mt][nt][0] * s0 + acc[mt][nt][1] * s1;
                pd[mt][0][hh] += acc[mt][nt][0] * d0 + acc[mt][nt][1] * d1;
                ps[mt][1][hh] += acc[mt][nt][2] * s0 + acc[mt][nt][3] * s1;
                pd[mt][1][hh] += acc[mt][nt][2] * d0 + acc[mt][nt][3] * d1;
                if (r0 < nrows)
                    *(float2*)(g_h + (size_t)r0 * 128 + col) =
                        make_float2(acc[mt][nt][0], acc[mt][nt][1]);
                if (r1 < nrows)
                    *(float2*)(g_h + (size_t)r1 * 128 + col) =
                        make_float2(acc[mt][nt][2], acc[mt][nt][3]);
            }
        }
        // reduce over t (lanes g*4 + {0..3})
        #pragma unroll
        for (int mt = 0; mt < 2; mt++)
            #pragma unroll
            for (int rs = 0; rs < 2; rs++)
                #pragma unroll
                for (int hh = 0; hh < 2; hh++) {
                    float vs = ps[mt][rs][hh];
                    float vd = pd[mt][rs][hh];
                    vs += __shfl_xor_sync(0xffffffffu, vs, 1);
                    vs += __shfl_xor_sync(0xffffffffu, vs, 2);
                    vd += __shfl_xor_sync(0xffffffffu, vd, 1);
                    vd += __shfl_xor_sync(0xffffffffu, vd, 2);
                    if (t == 0) {
                        int r = gr0 + mt * 16 + g + rs * 8;
                        if (r < nrows) {
                            int head = ni * 2 + hh;
                            g_asrc[r * 4 + head] = vs;
                            g_adst[r * 4 + head] = vd;
                        }
                    }
                }
    } else {
        int cb = nbase - 128;
        #pragma unroll
        for (int mt = 0; mt < 2; mt++) {
            int r0 = gr0 + mt * 16 + g;
            int r1 = r0 + 8;
            #pragma unroll
            for (int nt = 0; nt < 8; nt++) {
                int col = cb + nt * 8 + t * 2;
                if (r0 < nrows)
                    *(float2*)(g_skip + (size_t)r0 * 128 + col) =
                        make_float2(acc[mt][nt][0], acc[mt][nt][1]);
                if (r1 < nrows)
                    *(float2*)(g_skip + (size_t)r1 * 128 + col) =
                        make_float2(acc[mt][nt][2], acc[mt][nt][3]);
            }
        }
    }
}

// ------------------- softmax-aggregate + skip + bias + elu -------------------
__global__ void __launch_bounds__(256)
agg_kernel(const float* __restrict__ bias, float* __restrict__ out, int N) {
    int gw = (blockIdx.x * blockDim.x + threadIdx.x) >> 5;
    int lane = threadIdx.x & 31;
    if (gw >= N) return;
    int n = gw;
    int beg = g_off[n];
    int end = g_off[n + 1];
    int head = lane >> 3;

    float ad0 = g_adst[n * 4 + 0];
    float ad1 = g_adst[n * 4 + 1];
    float ad2 = g_adst[n * 4 + 2];
    float ad3 = g_adst[n * 4 + 3];

    float m0 = -INFINITY, m1 = -INFINITY, m2 = -INFINITY, m3 = -INFINITY;
    for (int i = beg + lane; i < end; i += 32) {
        int s = g_csr[i];
        float4 as = ((const float4*)g_asrc)[s];
        float e0 = as.x + ad0; e0 = (e0 > 0.f) ? e0 : NEG_SLOPE * e0;
        float e1 = as.y + ad1; e1 = (e1 > 0.f) ? e1 : NEG_SLOPE * e1;
        float e2 = as.z + ad2; e2 = (e2 > 0.f) ? e2 : NEG_SLOPE * e2;
        float e3 = as.w + ad3; e3 = (e3 > 0.f) ? e3 : NEG_SLOPE * e3;
        m0 = fmaxf(m0, e0); m1 = fmaxf(m1, e1); m2 = fmaxf(m2, e2); m3 = fmaxf(m3, e3);
    }
    #pragma unroll
    for (int o = 16; o > 0; o >>= 1) {
        m0 = fmaxf(m0, __shfl_xor_sync(0xffffffffu, m0, o));
        m1 = fmaxf(m1, __shfl_xor_sync(0xffffffffu, m1, o));
        m2 = fmaxf(m2, __shfl_xor_sync(0xffffffffu, m2, o));
        m3 = fmaxf(m3, __shfl_xor_sync(0xffffffffu, m3, o));
    }
    float mh  = (head == 0) ? m0 : (head == 1) ? m1 : (head == 2) ? m2 : m3;
    float adh = (head == 0) ? ad0 : (head == 1) ? ad1 : (head == 2) ? ad2 : ad3;

    float denom = 0.0f;
    float4 acc = make_float4(0.f, 0.f, 0.f, 0.f);
    const float4* h4 = (const float4*)g_h;
    for (int j = beg; j < end; j++) {
        int s = g_csr[j];
        float a = g_asrc[s * 4 + head];
        float e = a + adh; e = (e > 0.f) ? e : NEG_SLOPE * e;
        float w = __expf(e - mh);
        denom += w;
        float4 v = h4[(size_t)s * 32 + lane];
        acc.x += w * v.x; acc.y += w * v.y; acc.z += w * v.z; acc.w += w * v.w;
    }
    float inv = 1.0f / (denom + 1e-16f);
    float4 b  = ((const float4*)bias)[lane];
    float4 sk = ((const float4*)g_skip)[(size_t)n * 32 + lane];
    float4 o;
    o.x = acc.x * inv + b.x + sk.x;
    o.y = acc.y * inv + b.y + sk.y;
    o.z = acc.z * inv + b.z + sk.z;
    o.w = acc.w * inv + b.w + sk.w;
    o.x = (o.x > 0.f) ? o.x : expm1f(o.x);
    o.y = (o.y > 0.f) ? o.y : expm1f(o.y);
    o.z = (o.z > 0.f) ? o.z : expm1f(o.z);
    o.w = (o.w > 0.f) ? o.w : expm1f(o.w);
    ((float4*)out)[(size_t)n * 32 + lane] = o;
}

// ------------------- launch -------------------
extern "C" void kernel_launch(void* const* d_in, const int* in_sizes, int n_in,
                              void* d_out, int out_size) {
    const float* x    = (const float*)d_in[0];
    const int*   ei   = (const int*)  d_in[1];
    const float* W1   = (const float*)d_in[2];
    const float* as1  = (const float*)d_in[3];
    const float* ad1  = (const float*)d_in[4];
    const float* b1   = (const float*)d_in[5];
    const float* Ws1  = (const float*)d_in[6];
    const float* W2   = (const float*)d_in[7];
    const float* as2  = (const float*)d_in[8];
    const float* ad2  = (const float*)d_in[9];
    const float* b2   = (const float*)d_in[10];
    const float* Ws2  = (const float*)d_in[11];

    int N = in_sizes[0] / DIM;
    int E = in_sizes[1] / 2;
    const int* src = ei;
    const int* dst = ei + E;

    float* buf1;  cudaGetSymbolAddress((void**)&buf1, g_buf1);
    __nv_bfloat16* bhi; cudaGetSymbolAddress((void**)&bhi, g_bhi);
    __nv_bfloat16* blo; cudaGetSymbolAddress((void**)&blo, g_blo);

    const size_t dyn = 27136 * 4;  // 108544 B
    cudaFuncSetAttribute(gat_mma_fused, cudaFuncAttributeMaxDynamicSharedMemorySize, (int)dyn);

    prep_weights<<<(2 * 256 * 128 + 255) / 256, 256>>>(W1, Ws1, W2, Ws2);
    init_deg_kernel<<<(N + 255) / 256, 256>>>(N);
    hist_kernel<<<(E + 255) / 256, 256>>>(dst, E);
    scan_kernel<<<1, 1024>>>(N);
    scatter_kernel<<<(E + N + 255) / 256, 256>>>(src, dst, E, N);

    int gemm_blocks = (N + 63) / 64;
    int warp_blocks = (N * 32 + 255) / 256;

    // --- layer 1 ---
    gat_mma_fused<<<gemm_blocks, 256, dyn>>>(
        x, (const uint32_t*)bhi, (const uint32_t*)blo, as1, ad1, N);
    agg_kernel<<<warp_blocks, 256>>>(b1, buf1, N);

    // --- layer 2 ---
    gat_mma_fused<<<gemm_blocks, 256, dyn>>>(
        buf1, (const uint32_t*)(bhi + 256 * 128), (const uint32_t*)(blo + 256 * 128), as2, ad2, N);
    agg_kernel<<<warp_blocks, 256>>>(b2, (float*)d_out, N);
}

// round 4
// speedup vs baseline: 1.8689x; 1.3121x over previous
#include <cuda_runtime.h>
#include <cuda_bf16.h>
#include <stdint.h>
#include <math.h>

#define DIM 128
#define HEADS 4
#define NEG_SLOPE 0.2f
#define MAX_N 50000
#define MAX_E 600000
#define SCAN_CHUNK 1024   // elems per block in the multi-block scan
#define MAX_NB ((MAX_N + SCAN_CHUNK - 1) / SCAN_CHUNK)

// ------------------- scratch (static device globals; no allocs) -------------------
__device__ float g_h[MAX_N * DIM];
__device__ float g_skip[MAX_N * DIM];
__device__ float g_buf1[MAX_N * DIM];
__device__ float g_asrc[MAX_N * HEADS];
__device__ float g_adst[MAX_N * HEADS];
__device__ int   g_deg[MAX_N];
__device__ int   g_off[MAX_N + 1];
__device__ int   g_cursor[MAX_N];
__device__ int   g_csr[MAX_E + MAX_N];
__device__ int   g_bsum[MAX_NB];
__device__ int   g_bpre[MAX_NB];
// combined transposed weights per layer: Bt[n][k]: n<128 -> W[k][n], else Wskip[k][n-128]
__device__ __nv_bfloat16 g_bhi[2 * 256 * 128];
__device__ __nv_bfloat16 g_blo[2 * 256 * 128];

// ------------------- weight prep -------------------
__global__ void prep_weights(const float* __restrict__ W1, const float* __restrict__ Ws1,
                             const float* __restrict__ W2, const float* __restrict__ Ws2) {
    int idx = blockIdx.x * blockDim.x + threadIdx.x;
    if (idx >= 2 * 256 * 128) return;
    int layer = idx >> 15;
    int rem   = idx & 32767;
    int n     = rem >> 7;
    int k     = rem & 127;
    const float* W = layer ? (n < 128 ? W2 : Ws2) : (n < 128 ? W1 : Ws1);
    float v = W[k * 128 + (n & 127)];
    __nv_bfloat16 hi = __float2bfloat16(v);
    float lo = v - __bfloat162float(hi);
    g_bhi[idx] = hi;
    g_blo[idx] = __float2bfloat16(lo);
}

// ------------------- CSR build -------------------
__global__ void init_deg_kernel(int N) {
    int i = blockIdx.x * blockDim.x + threadIdx.x;
    if (i < N) g_deg[i] = 1;  // self-loop
}

__global__ void hist_kernel(const int* __restrict__ dst, int E) {
    int i = blockIdx.x * blockDim.x + threadIdx.x;
    if (i < E) atomicAdd(&g_deg[dst[i]], 1);
}

// ---- 3-phase multi-block scan ----
__global__ void scan_phase1(int N) {
    __shared__ int wsum[8];
    int tid = threadIdx.x;
    int lane = tid & 31, warp = tid >> 5;
    int i0 = blockIdx.x * SCAN_CHUNK + tid * 4;
    int s = 0;
    if (i0 + 3 < N) {
        int4 d = *(const int4*)(g_deg + i0);
        s = d.x + d.y + d.z + d.w;
    } else {
        for (int j = 0; j < 4; j++)
            if (i0 + j < N) s += g_deg[i0 + j];
    }
    #pragma unroll
    for (int o = 16; o > 0; o >>= 1) s += __shfl_xor_sync(0xffffffffu, s, o);
    if (lane == 0) wsum[warp] = s;
    __syncthreads();
    if (tid == 0) {
        int t = 0;
        #pragma unroll
        for (int w = 0; w < 8; w++) t += wsum[w];
        g_bsum[blockIdx.x] = t;
    }
}

__global__ void scan_bsums(int nb) {
    __shared__ int w0tot;
    int tid = threadIdx.x;  // 64 threads
    int lane = tid & 31;
    int orig = (tid < nb) ? g_bsum[tid] : 0;
    int v = orig;
    #pragma unroll
    for (int o = 1; o < 32; o <<= 1) {
        int t = __shfl_up_sync(0xffffffffu, v, o);
        if (lane >= o) v += t;
    }
    if (tid == 31) w0tot = v;
    __syncthreads();
    if (tid >= 32) v += w0tot;
    if (tid < nb) g_bpre[tid] = v - orig;  // exclusive
}

__global__ void scan_phase3(int N) {
    __shared__ int wsum[8];
    int tid = threadIdx.x;
    int lane = tid & 31, warp = tid >> 5;
    int i0 = blockIdx.x * SCAN_CHUNK + tid * 4;
    int4 d = make_int4(0, 0, 0, 0);
    if (i0 + 3 < N) {
        d = *(const int4*)(g_deg + i0);
    } else {
        if (i0 + 0 < N) d.x = g_deg[i0 + 0];
        if (i0 + 1 < N) d.y = g_deg[i0 + 1];
        if (i0 + 2 < N) d.z = g_deg[i0 + 2];
        if (i0 + 3 < N) d.w = g_deg[i0 + 3];
    }
    int T = d.x + d.y + d.z + d.w;
    // inclusive scan of T over the block
    int v = T;
    #pragma unroll
    for (int o = 1; o < 32; o <<= 1) {
        int t = __shfl_up_sync(0xffffffffu, v, o);
        if (lane >= o) v += t;
    }
    if (lane == 31) wsum[warp] = v;
    __syncthreads();
    if (warp == 0) {
        int w = (lane < 8) ? wsum[lane] : 0;
        #pragma unroll
        for (int o = 1; o < 8; o <<= 1) {
            int t = __shfl_up_sync(0xffffffffu, w, o);
            if (lane >= o) w += t;
        }
        if (lane < 8) wsum[lane] = w;
    }
    __syncthreads();
    int excl = v - T + (warp ? wsum[warp - 1] : 0) + g_bpre[blockIdx.x];
    int p = excl;
    if (i0 + 0 < N) { g_cursor[i0 + 0] = p; g_off[i0 + 1] = p + d.x; p += d.x; }
    if (i0 + 1 < N) { g_cursor[i0 + 1] = p; g_off[i0 + 2] = p + d.y; p += d.y; }
    if (i0 + 2 < N) { g_cursor[i0 + 2] = p; g_off[i0 + 3] = p + d.z; p += d.z; }
    if (i0 + 3 < N) { g_cursor[i0 + 3] = p; g_off[i0 + 4] = p + d.w; }
    if (blockIdx.x == 0 && tid == 0) g_off[0] = 0;
}

__global__ void scatter_kernel(const int* __restrict__ src, const int* __restrict__ dst,
                               int E, int N) {
    int i = blockIdx.x * blockDim.x + threadIdx.x;
    if (i < E) {
        int d = dst[i];
        int p = atomicAdd(&g_cursor[d], 1);
        g_csr[p] = src[i];
    } else if (i < E + N) {
        int n = i - E;
        int p = atomicAdd(&g_cursor[n], 1);
        g_csr[p] = n;
    }
}

// ------------------- HMMA helper -------------------
__device__ __forceinline__ void mma_bf16(float c[4], const uint32_t a[4], const uint32_t b[2]) {
    asm volatile(
        "mma.sync.aligned.m16n8k16.row.col.f32.bf16.bf16.f32 "
        "{%0,%1,%2,%3}, {%4,%5,%6,%7}, {%8,%9}, {%0,%1,%2,%3};"
        : "+f"(c[0]), "+f"(c[1]), "+f"(c[2]), "+f"(c[3])
        : "r"(a[0]), "r"(a[1]), "r"(a[2]), "r"(a[3]), "r"(b[0]), "r"(b[1]));
}

// ------------------- fused HMMA GEMM (h + skip) + attention logits -------------------
__global__ void __launch_bounds__(256, 2)
gat_mma_fused(const float* __restrict__ X,
              const uint32_t* __restrict__ Bhi, const uint32_t* __restrict__ Blo,
              const float* __restrict__ a_src, const float* __restrict__ a_dst,
              int nrows) {
    extern __shared__ uint32_t dsm[];
    __shared__ float s_att[256];
    uint32_t* Ah = dsm;            // 64*68
    uint32_t* Al = dsm + 4352;
    uint32_t* Bh = dsm + 8704;     // 256*36
    uint32_t* Bl = dsm + 17920;

    int tid  = threadIdx.x;
    int row0 = blockIdx.x * 64;
    if (tid < 128) { s_att[tid] = a_src[tid]; s_att[128 + tid] = a_dst[tid]; }

    #pragma unroll
    for (int it = 0; it < 16; it++) {
        int idx = tid + it * 256;
        int r = idx >> 6;
        int w = idx & 63;
        float x0 = 0.f, x1 = 0.f;
        int gr = row0 + r;
        if (gr < nrows) {
            float2 v = *(const float2*)(X + (size_t)gr * 128 + w * 2);
            x0 = v.x; x1 = v.y;
        }
        __nv_bfloat16 h0 = __float2bfloat16(x0);
        __nv_bfloat16 h1 = __float2bfloat16(x1);
        __nv_bfloat16 l0 = __float2bfloat16(x0 - __bfloat162float(h0));
        __nv_bfloat16 l1 = __float2bfloat16(x1 - __bfloat162float(h1));
        Ah[r * 68 + w] = ((uint32_t)__bfloat16_as_ushort(h1) << 16) | __bfloat16_as_ushort(h0);
        Al[r * 68 + w] = ((uint32_t)__bfloat16_as_ushort(l1) << 16) | __bfloat16_as_ushort(l0);
    }

    int lane = tid & 31, warp = tid >> 5;
    int mi = warp & 1, ni = warp >> 1;
    int g = lane >> 2, t = lane & 3;
    int mloc  = mi * 32;
    int nbase = ni * 64;

    float acc[2][8][4];
    #pragma unroll
    for (int a = 0; a < 2; a++)
        #pragma unroll
        for (int b = 0; b < 8; b++)
            #pragma unroll
            for (int c = 0; c < 4; c++) acc[a][b][c] = 0.f;

    for (int kc = 0; kc < 2; kc++) {
        if (kc) __syncthreads();
        #pragma unroll
        for (int it = 0; it < 32; it++) {
            int idx = tid + it * 256;
            int r = idx >> 5;
            int w = idx & 31;
            Bh[r * 36 + w] = Bhi[r * 64 + kc * 32 + w];
            Bl[r * 36 + w] = Blo[r * 64 + kc * 32 + w];
        }
        __syncthreads();

        #pragma unroll
        for (int p = 0; p < 3; p++) {
            const uint32_t* As = (p == 2) ? Al : Ah;
            const uint32_t* Bs = (p == 1) ? Bl : Bh;
            #pragma unroll
            for (int ksl = 0; ksl < 4; ksl++) {
                int aw = kc * 32 + ksl * 8 + t;
                uint32_t af[2][4];
                #pragma unroll
                for (int mt = 0; mt < 2; mt++) {
                    int rb = (mloc + mt * 16 + g) * 68;
                    af[mt][0] = As[rb + aw];
                    af[mt][1] = As[rb + 8 * 68 + aw];
                    af[mt][2] = As[rb + aw + 4];
                    af[mt][3] = As[rb + 8 * 68 + aw + 4];
                }
                int bw = ksl * 8 + t;
                #pragma unroll
                for (int nt = 0; nt < 8; nt++) {
                    uint32_t bf[2];
                    int rb = (nbase + nt * 8 + g) * 36;
                    bf[0] = Bs[rb + bw];
                    bf[1] = Bs[rb + bw + 4];
                    mma_bf16(acc[0][nt], af[0], bf);
                    mma_bf16(acc[1][nt], af[1], bf);
                }
            }
        }
    }

    int gr0 = row0 + mloc;
    if (ni < 2) {
        float ps[2][2][2], pd[2][2][2];
        #pragma unroll
        for (int a = 0; a < 2; a++)
            #pragma unroll
            for (int b = 0; b < 2; b++) {
                ps[a][b][0] = ps[a][b][1] = 0.f;
                pd[a][b][0] = pd[a][b][1] = 0.f;
            }
        #pragma unroll
        for (int mt = 0; mt < 2; mt++) {
            int r0 = gr0 + mt * 16 + g;
            int r1 = r0 + 8;
            #pragma unroll
            for (int nt = 0; nt < 8; nt++) {
                int col = nbase + nt * 8 + t * 2;
                int hh = nt >> 2;
                float s0 = s_att[col],       s1 = s_att[col + 1];
                float d0 = s_att[128 + col], d1 = s_att[128 + col + 1];
                ps[mt][0][hh] += acc[mt][nt][0] * s0 + acc[mt][nt][1] * s1;
                pd[mt][0][hh] += acc[mt][nt][0] * d0 + acc[mt][nt][1] * d1;
                ps[mt][1][hh] += acc[mt][nt][2] * s0 + acc[mt][nt][3] * s1;
                pd[mt][1][hh] += acc[mt][nt][2] * d0 + acc[mt][nt][3] * d1;
                if (r0 < nrows)
                    *(float2*)(g_h + (size_t)r0 * 128 + col) =
                        make_float2(acc[mt][nt][0], acc[mt][nt][1]);
                if (r1 < nrows)
                    *(float2*)(g_h + (size_t)r1 * 128 + col) =
                        make_float2(acc[mt][nt][2], acc[mt][nt][3]);
            }
        }
        #pragma unroll
        for (int mt = 0; mt < 2; mt++)
            #pragma unroll
            for (int rs = 0; rs < 2; rs++)
                #pragma unroll
                for (int hh = 0; hh < 2; hh++) {
                    float vs = ps[mt][rs][hh];
                    float vd = pd[mt][rs][hh];
                    vs += __shfl_xor_sync(0xffffffffu, vs, 1);
                    vs += __shfl_xor_sync(0xffffffffu, vs, 2);
                    vd += __shfl_xor_sync(0xffffffffu, vd, 1);
                    vd += __shfl_xor_sync(0xffffffffu, vd, 2);
                    if (t == 0) {
                        int r = gr0 + mt * 16 + g + rs * 8;
                        if (r < nrows) {
                            int head = ni * 2 + hh;
                            g_asrc[r * 4 + head] = vs;
                            g_adst[r * 4 + head] = vd;
                        }
                    }
                }
    } else {
        int cb = nbase - 128;
        #pragma unroll
        for (int mt = 0; mt < 2; mt++) {
            int r0 = gr0 + mt * 16 + g;
            int r1 = r0 + 8;
            #pragma unroll
            for (int nt = 0; nt < 8; nt++) {
                int col = cb + nt * 8 + t * 2;
                if (r0 < nrows)
                    *(float2*)(g_skip + (size_t)r0 * 128 + col) =
                        make_float2(acc[mt][nt][0], acc[mt][nt][1]);
                if (r1 < nrows)
                    *(float2*)(g_skip + (size_t)r1 * 128 + col) =
                        make_float2(acc[mt][nt][2], acc[mt][nt][3]);
            }
        }
    }
}

// ------------------- softmax-aggregate + skip + bias + elu -------------------
__global__ void __launch_bounds__(256)
agg_kernel(const float* __restrict__ bias, float* __restrict__ out, int N) {
    int gw = (blockIdx.x * blockDim.x + threadIdx.x) >> 5;
    int lane = threadIdx.x & 31;
    if (gw >= N) return;
    int n = gw;
    int beg = g_off[n];
    int end = g_off[n + 1];
    int head = lane >> 3;

    float ad0 = g_adst[n * 4 + 0];
    float ad1 = g_adst[n * 4 + 1];
    float ad2 = g_adst[n * 4 + 2];
    float ad3 = g_adst[n * 4 + 3];

    float m0 = -INFINITY, m1 = -INFINITY, m2 = -INFINITY, m3 = -INFINITY;
    for (int i = beg + lane; i < end; i += 32) {
        int s = g_csr[i];
        float4 as = ((const float4*)g_asrc)[s];
        float e0 = as.x + ad0; e0 = (e0 > 0.f) ? e0 : NEG_SLOPE * e0;
        float e1 = as.y + ad1; e1 = (e1 > 0.f) ? e1 : NEG_SLOPE * e1;
        float e2 = as.z + ad2; e2 = (e2 > 0.f) ? e2 : NEG_SLOPE * e2;
        float e3 = as.w + ad3; e3 = (e3 > 0.f) ? e3 : NEG_SLOPE * e3;
        m0 = fmaxf(m0, e0); m1 = fmaxf(m1, e1); m2 = fmaxf(m2, e2); m3 = fmaxf(m3, e3);
    }
    #pragma unroll
    for (int o = 16; o > 0; o >>= 1) {
        m0 = fmaxf(m0, __shfl_xor_sync(0xffffffffu, m0, o));
        m1 = fmaxf(m1, __shfl_xor_sync(0xffffffffu, m1, o));
        m2 = fmaxf(m2, __shfl_xor_sync(0xffffffffu, m2, o));
        m3 = fmaxf(m3, __shfl_xor_sync(0xffffffffu, m3, o));
    }
    float mh  = (head == 0) ? m0 : (head == 1) ? m1 : (head == 2) ? m2 : m3;
    float adh = (head == 0) ? ad0 : (head == 1) ? ad1 : (head == 2) ? ad2 : ad3;

    float denom = 0.0f;
    float4 acc = make_float4(0.f, 0.f, 0.f, 0.f);
    const float4* h4 = (const float4*)g_h;
    for (int j = beg; j < end; j++) {
        int s = g_csr[j];
        float a = g_asrc[s * 4 + head];
        float e = a + adh; e = (e > 0.f) ? e : NEG_SLOPE * e;
        float w = __expf(e - mh);
        denom += w;
        float4 v = h4[(size_t)s * 32 + lane];
        acc.x += w * v.x; acc.y += w * v.y; acc.z += w * v.z; acc.w += w * v.w;
    }
    float inv = 1.0f / (denom + 1e-16f);
    float4 b  = ((const float4*)bias)[lane];
    float4 sk = ((const float4*)g_skip)[(size_t)n * 32 + lane];
    float4 o;
    o.x = acc.x * inv + b.x + sk.x;
    o.y = acc.y * inv + b.y + sk.y;
    o.z = acc.z * inv + b.z + sk.z;
    o.w = acc.w * inv + b.w + sk.w;
    o.x = (o.x > 0.f) ? o.x : expm1f(o.x);
    o.y = (o.y > 0.f) ? o.y : expm1f(o.y);
    o.z = (o.z > 0.f) ? o.z : expm1f(o.z);
    o.w = (o.w > 0.f) ? o.w : expm1f(o.w);
    ((float4*)out)[(size_t)n * 32 + lane] = o;
}

// ------------------- launch -------------------
extern "C" void kernel_launch(void* const* d_in, const int* in_sizes, int n_in,
                              void* d_out, int out_size) {
    const float* x    = (const float*)d_in[0];
    const int*   ei   = (const int*)  d_in[1];
    const float* W1   = (const float*)d_in[2];
    const float* as1  = (const float*)d_in[3];
    const float* ad1  = (const float*)d_in[4];
    const float* b1   = (const float*)d_in[5];
    const float* Ws1  = (const float*)d_in[6];
    const float* W2   = (const float*)d_in[7];
    const float* as2  = (const float*)d_in[8];
    const float* ad2  = (const float*)d_in[9];
    const float* b2   = (const float*)d_in[10];
    const float* Ws2  = (const float*)d_in[11];

    int N = in_sizes[0] / DIM;
    int E = in_sizes[1] / 2;
    const int* src = ei;
    const int* dst = ei + E;

    float* buf1;  cudaGetSymbolAddress((void**)&buf1, g_buf1);
    __nv_bfloat16* bhi; cudaGetSymbolAddress((void**)&bhi, g_bhi);
    __nv_bfloat16* blo; cudaGetSymbolAddress((void**)&blo, g_blo);

    const size_t dyn = 27136 * 4;
    cudaFuncSetAttribute(gat_mma_fused, cudaFuncAttributeMaxDynamicSharedMemorySize, (int)dyn);

    int nb = (N + SCAN_CHUNK - 1) / SCAN_CHUNK;

    prep_weights<<<(2 * 256 * 128 + 255) / 256, 256>>>(W1, Ws1, W2, Ws2);
    init_deg_kernel<<<(N + 255) / 256, 256>>>(N);
    hist_kernel<<<(E + 255) / 256, 256>>>(dst, E);
    scan_phase1<<<nb, 256>>>(N);
    scan_bsums<<<1, 64>>>(nb);
    scan_phase3<<<nb, 256>>>(N);
    scatter_kernel<<<(E + N + 255) / 256, 256>>>(src, dst, E, N);

    int gemm_blocks = (N + 63) / 64;
    int warp_blocks = (N * 32 + 255) / 256;

    // --- layer 1 ---
    gat_mma_fused<<<gemm_blocks, 256, dyn>>>(
        x, (const uint32_t*)bhi, (const uint32_t*)blo, as1, ad1, N);
    agg_kernel<<<warp_blocks, 256>>>(b1, buf1, N);

    // --- layer 2 ---
    gat_mma_fused<<<gemm_blocks, 256, dyn>>>(
        buf1, (const uint32_t*)(bhi + 256 * 128), (const uint32_t*)(blo + 256 * 128), as2, ad2, N);
    agg_kernel<<<warp_blocks, 256>>>(b2, (float*)d_out, N);
}

// round 5
// speedup vs baseline: 1.8723x; 1.0018x over previous
#include <cuda_runtime.h>
#include <cuda_bf16.h>
#include <stdint.h>
#include <math.h>

#define DIM 128
#define HEADS 4
#define NEG_SLOPE 0.2f
#define MAX_N 50000
#define MAX_E 600000
#define SCAN_CHUNK 1024
#define MAX_NB ((MAX_N + SCAN_CHUNK - 1) / SCAN_CHUNK)

// ------------------- scratch (static device globals; no allocs) -------------------
__device__ float g_h[MAX_N * DIM];
__device__ float g_skip[MAX_N * DIM];
__device__ float g_buf1[MAX_N * DIM];
__device__ float g_asrc[MAX_N * HEADS];
__device__ float g_adst[MAX_N * HEADS];
__device__ int   g_deg[MAX_N];
__device__ int   g_off[MAX_N + 1];
__device__ int   g_cursor[MAX_N];
__device__ int   g_csr[MAX_E + MAX_N];
__device__ int   g_agg[MAX_NB];
__device__ int   g_flag[MAX_NB];
// combined transposed weights per layer: Bt[n][k]: n<128 -> W[k][n], else Wskip[k][n-128]
__device__ __nv_bfloat16 g_bhi[2 * 256 * 128];
__device__ __nv_bfloat16 g_blo[2 * 256 * 128];

// ------------------- prep: weights + deg init + scan-flag reset (one kernel) -------------------
__global__ void prep_all(const float* __restrict__ W1, const float* __restrict__ Ws1,
                         const float* __restrict__ W2, const float* __restrict__ Ws2,
                         int N) {
    int idx = blockIdx.x * blockDim.x + threadIdx.x;
    if (idx < N) g_deg[idx] = 1;           // self-loop
    if (idx < MAX_NB) g_flag[idx] = 0;     // scan lookback flags
    if (idx >= 2 * 256 * 128) return;
    int layer = idx >> 15;
    int rem   = idx & 32767;
    int n     = rem >> 7;
    int k     = rem & 127;
    const float* W = layer ? (n < 128 ? W2 : Ws2) : (n < 128 ? W1 : Ws1);
    float v = W[k * 128 + (n & 127)];
    __nv_bfloat16 hi = __float2bfloat16(v);
    float lo = v - __bfloat162float(hi);
    g_bhi[idx] = hi;
    g_blo[idx] = __float2bfloat16(lo);
}

__global__ void hist_kernel(const int* __restrict__ dst, int E) {
    int i = blockIdx.x * blockDim.x + threadIdx.x;
    if (i < E) atomicAdd(&g_deg[dst[i]], 1);
}

// ------------------- single-kernel scan with decoupled lookback -------------------
// grid = nb (<=49) blocks x 256 threads, 4 elems/thread. All blocks resident -> spin safe.
__global__ void scan_lookback(int N) {
    __shared__ int wsum[8];
    __shared__ int s_base;
    int tid = threadIdx.x;
    int lane = tid & 31, warp = tid >> 5;
    int b = blockIdx.x;
    int i0 = b * SCAN_CHUNK + tid * 4;

    int4 d = make_int4(0, 0, 0, 0);
    if (i0 + 3 < N) {
        d = *(const int4*)(g_deg + i0);
    } else {
        if (i0 + 0 < N) d.x = g_deg[i0 + 0];
        if (i0 + 1 < N) d.y = g_deg[i0 + 1];
        if (i0 + 2 < N) d.z = g_deg[i0 + 2];
        if (i0 + 3 < N) d.w = g_deg[i0 + 3];
    }
    int T = d.x + d.y + d.z + d.w;
    int v = T;
    #pragma unroll
    for (int o = 1; o < 32; o <<= 1) {
        int t = __shfl_up_sync(0xffffffffu, v, o);
        if (lane >= o) v += t;
    }
    if (lane == 31) wsum[warp] = v;
    __syncthreads();
    if (warp == 0) {
        int w = (lane < 8) ? wsum[lane] : 0;
        #pragma unroll
        for (int o = 1; o < 8; o <<= 1) {
            int t = __shfl_up_sync(0xffffffffu, w, o);
            if (lane >= o) w += t;
        }
        if (lane < 8) wsum[lane] = w;
        // publish this block's aggregate
        if (lane == 0) {
            g_agg[b] = wsum[7];
            __threadfence();
            atomicExch(&g_flag[b], 1);
        }
    }
    __syncthreads();
    int blk_total_scan = (warp ? wsum[warp - 1] : 0);

    // lookback: warp 0 sums aggregates of blocks [0, b)
    if (warp == 0) {
        int base = 0;
        for (int i = lane; i < b; i += 32) {
            while (atomicAdd(&g_flag[i], 0) == 0) {}
            base += g_agg[i];
        }
        #pragma unroll
        for (int o = 16; o > 0; o >>= 1) base += __shfl_xor_sync(0xffffffffu, base, o);
        if (lane == 0) s_base = base;
    }
    __syncthreads();

    int excl = v - T + blk_total_scan + s_base;
    int p = excl;
    if (i0 + 0 < N) { g_cursor[i0 + 0] = p; g_off[i0 + 1] = p + d.x; p += d.x; }
    if (i0 + 1 < N) { g_cursor[i0 + 1] = p; g_off[i0 + 2] = p + d.y; p += d.y; }
    if (i0 + 2 < N) { g_cursor[i0 + 2] = p; g_off[i0 + 3] = p + d.z; p += d.z; }
    if (i0 + 3 < N) { g_cursor[i0 + 3] = p; g_off[i0 + 4] = p + d.w; }
    if (b == 0 && tid == 0) g_off[0] = 0;
}

__global__ void scatter_kernel(const int* __restrict__ src, const int* __restrict__ dst,
                               int E, int N) {
    int i = blockIdx.x * blockDim.x + threadIdx.x;
    if (i < E) {
        int d = dst[i];
        int p = atomicAdd(&g_cursor[d], 1);
        g_csr[p] = src[i];
    } else if (i < E + N) {
        int n = i - E;
        int p = atomicAdd(&g_cursor[n], 1);
        g_csr[p] = n;
    }
}

// ------------------- HMMA helper -------------------
__device__ __forceinline__ void mma_bf16(float c[4], const uint32_t a[4], const uint32_t b[2]) {
    asm volatile(
        "mma.sync.aligned.m16n8k16.row.col.f32.bf16.bf16.f32 "
        "{%0,%1,%2,%3}, {%4,%5,%6,%7}, {%8,%9}, {%0,%1,%2,%3};"
        : "+f"(c[0]), "+f"(c[1]), "+f"(c[2]), "+f"(c[3])
        : "r"(a[0]), "r"(a[1]), "r"(a[2]), "r"(a[3]), "r"(b[0]), "r"(b[1]));
}

// ------------------- fused HMMA GEMM (h + skip) + attention logits -------------------
__global__ void __launch_bounds__(256, 2)
gat_mma_fused(const float* __restrict__ X,
              const uint32_t* __restrict__ Bhi, const uint32_t* __restrict__ Blo,
              const float* __restrict__ a_src, const float* __restrict__ a_dst,
              int nrows) {
    extern __shared__ uint32_t dsm[];
    __shared__ float s_att[256];
    uint32_t* Ah = dsm;            // 64*68
    uint32_t* Al = dsm + 4352;
    uint32_t* Bh = dsm + 8704;     // 256*36
    uint32_t* Bl = dsm + 17920;

    int tid  = threadIdx.x;
    int row0 = blockIdx.x * 64;
    if (tid < 128) { s_att[tid] = a_src[tid]; s_att[128 + tid] = a_dst[tid]; }

    #pragma unroll
    for (int it = 0; it < 16; it++) {
        int idx = tid + it * 256;
        int r = idx >> 6;
        int w = idx & 63;
        float x0 = 0.f, x1 = 0.f;
        int gr = row0 + r;
        if (gr < nrows) {
            float2 v = *(const float2*)(X + (size_t)gr * 128 + w * 2);
            x0 = v.x; x1 = v.y;
        }
        __nv_bfloat16 h0 = __float2bfloat16(x0);
        __nv_bfloat16 h1 = __float2bfloat16(x1);
        __nv_bfloat16 l0 = __float2bfloat16(x0 - __bfloat162float(h0));
        __nv_bfloat16 l1 = __float2bfloat16(x1 - __bfloat162float(h1));
        Ah[r * 68 + w] = ((uint32_t)__bfloat16_as_ushort(h1) << 16) | __bfloat16_as_ushort(h0);
        Al[r * 68 + w] = ((uint32_t)__bfloat16_as_ushort(l1) << 16) | __bfloat16_as_ushort(l0);
    }

    int lane = tid & 31, warp = tid >> 5;
    int mi = warp & 1, ni = warp >> 1;
    int g = lane >> 2, t = lane & 3;
    int mloc  = mi * 32;
    int nbase = ni * 64;

    float acc[2][8][4];
    #pragma unroll
    for (int a = 0; a < 2; a++)
        #pragma unroll
        for (int b = 0; b < 8; b++)
            #pragma unroll
            for (int c = 0; c < 4; c++) acc[a][b][c] = 0.f;

    for (int kc = 0; kc < 2; kc++) {
        if (kc) __syncthreads();
        #pragma unroll
        for (int it = 0; it < 32; it++) {
            int idx = tid + it * 256;
            int r = idx >> 5;
            int w = idx & 31;
            Bh[r * 36 + w] = Bhi[r * 64 + kc * 32 + w];
            Bl[r * 36 + w] = Blo[r * 64 + kc * 32 + w];
        }
        __syncthreads();

        #pragma unroll
        for (int p = 0; p < 3; p++) {
            const uint32_t* As = (p == 2) ? Al : Ah;
            const uint32_t* Bs = (p == 1) ? Bl : Bh;
            #pragma unroll
            for (int ksl = 0; ksl < 4; ksl++) {
                int aw = kc * 32 + ksl * 8 + t;
                uint32_t af[2][4];
                #pragma unroll
                for (int mt = 0; mt < 2; mt++) {
                    int rb = (mloc + mt * 16 + g) * 68;
                    af[mt][0] = As[rb + aw];
                    af[mt][1] = As[rb + 8 * 68 + aw];
                    af[mt][2] = As[rb + aw + 4];
                    af[mt][3] = As[rb + 8 * 68 + aw + 4];
                }
                int bw = ksl * 8 + t;
                #pragma unroll
                for (int nt = 0; nt < 8; nt++) {
                    uint32_t bf[2];
                    int rb = (nbase + nt * 8 + g) * 36;
                    bf[0] = Bs[rb + bw];
                    bf[1] = Bs[rb + bw + 4];
                    mma_bf16(acc[0][nt], af[0], bf);
                    mma_bf16(acc[1][nt], af[1], bf);
                }
            }
        }
    }

    int gr0 = row0 + mloc;
    if (ni < 2) {
        float ps[2][2][2], pd[2][2][2];
        #pragma unroll
        for (int a = 0; a < 2; a++)
            #pragma unroll
            for (int b = 0; b < 2; b++) {
                ps[a][b][0] = ps[a][b][1] = 0.f;
                pd[a][b][0] = pd[a][b][1] = 0.f;
            }
        #pragma unroll
        for (int mt = 0; mt < 2; mt++) {
            int r0 = gr0 + mt * 16 + g;
            int r1 = r0 + 8;
            #pragma unroll
            for (int nt = 0; nt < 8; nt++) {
                int col = nbase + nt * 8 + t * 2;
                int hh = nt >> 2;
                float s0 = s_att[col],       s1 = s_att[col + 1];
                float d0 = s_att[128 + col], d1 = s_att[128 + col + 1];
                ps[mt][0][hh] += acc[mt][nt][0] * s0 + acc[mt][nt][1] * s1;
                pd[mt][0][hh] += acc[mt][nt][0] * d0 + acc[mt][nt][1] * d1;
                ps[mt][1][hh] += acc[mt][nt][2] * s0 + acc[mt][nt][3] * s1;
                pd[mt][1][hh] += acc[mt][nt][2] * d0 + acc[mt][nt][3] * d1;
                if (r0 < nrows)
                    *(float2*)(g_h + (size_t)r0 * 128 + col) =
                        make_float2(acc[mt][nt][0], acc[mt][nt][1]);
                if (r1 < nrows)
                    *(float2*)(g_h + (size_t)r1 * 128 + col) =
                        make_float2(acc[mt][nt][2], acc[mt][nt][3]);
            }
        }
        #pragma unroll
        for (int mt = 0; mt < 2; mt++)
            #pragma unroll
            for (int rs = 0; rs < 2; rs++)
                #pragma unroll
                for (int hh = 0; hh < 2; hh++) {
                    float vs = ps[mt][rs][hh];
                    float vd = pd[mt][rs][hh];
                    vs += __shfl_xor_sync(0xffffffffu, vs, 1);
                    vs += __shfl_xor_sync(0xffffffffu, vs, 2);
                    vd += __shfl_xor_sync(0xffffffffu, vd, 1);
                    vd += __shfl_xor_sync(0xffffffffu, vd, 2);
                    if (t == 0) {
                        int r = gr0 + mt * 16 + g + rs * 8;
                        if (r < nrows) {
                            int head = ni * 2 + hh;
                            g_asrc[r * 4 + head] = vs;
                            g_adst[r * 4 + head] = vd;
                        }
                    }
                }
    } else {
        int cb = nbase - 128;
        #pragma unroll
        for (int mt = 0; mt < 2; mt++) {
            int r0 = gr0 + mt * 16 + g;
            int r1 = r0 + 8;
            #pragma unroll
            for (int nt = 0; nt < 8; nt++) {
                int col = cb + nt * 8 + t * 2;
                if (r0 < nrows)
                    *(float2*)(g_skip + (size_t)r0 * 128 + col) =
                        make_float2(acc[mt][nt][0], acc[mt][nt][1]);
                if (r1 < nrows)
                    *(float2*)(g_skip + (size_t)r1 * 128 + col) =
                        make_float2(acc[mt][nt][2], acc[mt][nt][3]);
            }
        }
    }
}

// ------------------- online-softmax aggregate + skip + bias + elu -------------------
// warp per node, single pass: running max with rescale (flash-style).
__global__ void __launch_bounds__(256)
agg_kernel(const float* __restrict__ bias, float* __restrict__ out, int N) {
    int gw = (blockIdx.x * blockDim.x + threadIdx.x) >> 5;
    int lane = threadIdx.x & 31;
    if (gw >= N) return;
    int n = gw;
    int beg = g_off[n];
    int end = g_off[n + 1];
    int head = lane >> 3;

    float adh = g_adst[n * 4 + head];

    float m = -INFINITY;
    float denom = 0.0f;
    float4 acc = make_float4(0.f, 0.f, 0.f, 0.f);
    const float4* h4 = (const float4*)g_h;
    for (int j = beg; j < end; j++) {
        int s = g_csr[j];                       // broadcast
        float a = g_asrc[s * 4 + head];         // 4 distinct addrs / warp
        float e = a + adh; e = (e > 0.f) ? e : NEG_SLOPE * e;
        float4 v = h4[(size_t)s * 32 + lane];   // coalesced 512B/warp
        float mn = fmaxf(m, e);
        float sc = __expf(m - mn);              // 1 when max unchanged
        float w  = __expf(e - mn);
        denom = denom * sc + w;
        acc.x = acc.x * sc + w * v.x;
        acc.y = acc.y * sc + w * v.y;
        acc.z = acc.z * sc + w * v.z;
        acc.w = acc.w * sc + w * v.w;
        m = mn;
    }
    float inv = 1.0f / (denom + 1e-16f);
    float4 b  = ((const float4*)bias)[lane];
    float4 sk = ((const float4*)g_skip)[(size_t)n * 32 + lane];
    float4 o;
    o.x = acc.x * inv + b.x + sk.x;
    o.y = acc.y * inv + b.y + sk.y;
    o.z = acc.z * inv + b.z + sk.z;
    o.w = acc.w * inv + b.w + sk.w;
    o.x = (o.x > 0.f) ? o.x : expm1f(o.x);
    o.y = (o.y > 0.f) ? o.y : expm1f(o.y);
    o.z = (o.z > 0.f) ? o.z : expm1f(o.z);
    o.w = (o.w > 0.f) ? o.w : expm1f(o.w);
    ((float4*)out)[(size_t)n * 32 + lane] = o;
}

// ------------------- launch -------------------
extern "C" void kernel_launch(void* const* d_in, const int* in_sizes, int n_in,
                              void* d_out, int out_size) {
    const float* x    = (const float*)d_in[0];
    const int*   ei   = (const int*)  d_in[1];
    const float* W1   = (const float*)d_in[2];
    const float* as1  = (const float*)d_in[3];
    const float* ad1  = (const float*)d_in[4];
    const float* b1   = (const float*)d_in[5];
    const float* Ws1  = (const float*)d_in[6];
    const float* W2   = (const float*)d_in[7];
    const float* as2  = (const float*)d_in[8];
    const float* ad2  = (const float*)d_in[9];
    const float* b2   = (const float*)d_in[10];
    const float* Ws2  = (const float*)d_in[11];

    int N = in_sizes[0] / DIM;
    int E = in_sizes[1] / 2;
    const int* src = ei;
    const int* dst = ei + E;

    float* buf1;  cudaGetSymbolAddress((void**)&buf1, g_buf1);
    __nv_bfloat16* bhi; cudaGetSymbolAddress((void**)&bhi, g_bhi);
    __nv_bfloat16* blo; cudaGetSymbolAddress((void**)&blo, g_blo);

    const size_t dyn = 27136 * 4;
    cudaFuncSetAttribute(gat_mma_fused, cudaFuncAttributeMaxDynamicSharedMemorySize, (int)dyn);

    int nb = (N + SCAN_CHUNK - 1) / SCAN_CHUNK;
    int gemm_blocks = (N + 63) / 64;
    int warp_blocks = (N * 32 + 255) / 256;

    // launch index:                                                   idx
    prep_all<<<256, 256>>>(W1, Ws1, W2, Ws2, N);                    // 0
    hist_kernel<<<(E + 255) / 256, 256>>>(dst, E);                  // 1
    scan_lookback<<<nb, 256>>>(N);                                  // 2
    scatter_kernel<<<(E + N + 255) / 256, 256>>>(src, dst, E, N);   // 3
    gat_mma_fused<<<gemm_blocks, 256, dyn>>>(                       // 4
        x, (const uint32_t*)bhi, (const uint32_t*)blo, as1, ad1, N);
    agg_kernel<<<warp_blocks, 256>>>(b1, buf1, N);                  // 5  <- profiled
    gat_mma_fused<<<gemm_blocks, 256, dyn>>>(                       // 6
        buf1, (const uint32_t*)(bhi + 256 * 128), (const uint32_t*)(blo + 256 * 128), as2, ad2, N);
    agg_kernel<<<warp_blocks, 256>>>(b2, (float*)d_out, N);         // 7
}